// round 17
// baseline (speedup 1.0000x reference)
#include <cuda_runtime.h>
#include <cstdint>
#include <math.h>

// Problem constants
#define BB    8
#define SS    2048
#define DIN   256
#define DIMN  256
#define GAMMA 0.9865
#define NCH   16          // chunks of 128 along sequence

// Linear-attention formulation (decay folded into Q/K):
//   Qt_i = Q_i * g^-i * s,  Kt_j = K_j * g^j * s   (s = sqrt(scoreScale))
//   diag_c = tril(Qt_c Kt_c^T);  denom[i] = rowsum(diag)[i] + Qt_i.ksumExcl[c]
//   V' = V / max(|denom|,1);  G_c = Kt_c^T V'_c;  S_c = excl prefix;
//   out_c = Qt_c @ S_c + diag_c @ V'_c
// ---------------------------------------------------------------------------
__device__ float g_Q[BB * SS * DIMN];
__device__ float g_K[BB * SS * DIMN];
__device__ float g_V[BB * SS * DIMN];
__device__ float g_KT[BB * DIMN * SS];
__device__ float g_G[BB * NCH * DIMN * DIMN];
__device__ float g_S[BB * NCH * DIMN * DIMN];
__device__ float g_diag[BB * NCH * 128 * 128];
__device__ float g_segsum[BB * 64 * DIMN];
__device__ float g_ksum[BB * NCH * DIMN];
__device__ float g_dsumP[2][BB * SS];                 // per-column-half diag row sums

__device__ __forceinline__ float4 ld4(const float* p) {
    return *reinterpret_cast<const float4*>(p);
}
__device__ __forceinline__ void splitu(float x, uint32_t& h, uint32_t& l) {
    uint32_t u;
    asm("cvt.rna.tf32.f32 %0, %1;" : "=r"(u) : "f"(x));
    h = u;
    l = __float_as_uint(x - __uint_as_float(u));
}
__device__ __forceinline__ uint32_t to_tf32(float x) {
    uint32_t u;
    asm("cvt.rna.tf32.f32 %0, %1;" : "=r"(u) : "f"(x));
    return u;
}
__device__ __forceinline__ void mma_tf32(float* c,
                                         uint32_t a0, uint32_t a1, uint32_t a2, uint32_t a3,
                                         uint32_t b0, uint32_t b1) {
    asm volatile(
        "mma.sync.aligned.m16n8k8.row.col.f32.tf32.tf32.f32 "
        "{%0,%1,%2,%3},{%4,%5,%6,%7},{%8,%9},{%0,%1,%2,%3};\n"
        : "+f"(c[0]), "+f"(c[1]), "+f"(c[2]), "+f"(c[3])
        : "r"(a0), "r"(a1), "r"(a2), "r"(a3), "r"(b0), "r"(b1));
}

// ---------------------------------------------------------------------------
// A smem: float4 aSm[16][32], XOR-swizzled fragments.
// ---------------------------------------------------------------------------
__device__ __forceinline__ void ldgA(const float* __restrict__ g, int ld, int row0, int k0,
                                     int t, float4 st[4]) {
    int ks = t >> 6, mg = (t >> 3) & 7, r = t & 7;
    const float* p = g + (size_t)(row0 + mg * 16 + r) * ld + (k0 + ks * 8);
    st[0] = ld4(p); st[1] = ld4(p + 4);
    p += (size_t)8 * ld;
    st[2] = ld4(p); st[3] = ld4(p + 4);
}
__device__ __forceinline__ void stsA(float4* aSm, int t, const float4 st[4]) {
    int ks = t >> 6, mg = (t >> 3) & 7, r = t & 7;
    int base = (ks * 8 + mg) * 32, sw = (r >> 1) & 3, r4 = r * 4;
    aSm[base + ((r4 + 0) ^ sw)] = make_float4(st[0].x, st[2].x, st[1].x, st[3].x);
    aSm[base + ((r4 + 1) ^ sw)] = make_float4(st[0].y, st[2].y, st[1].y, st[3].y);
    aSm[base + ((r4 + 2) ^ sw)] = make_float4(st[0].z, st[2].z, st[1].z, st[3].z);
    aSm[base + ((r4 + 3) ^ sw)] = make_float4(st[0].w, st[2].w, st[1].w, st[3].w);
}

// --------------------------- B smem, 64 cols ---------------------------------
__device__ __forceinline__ void ldgBD(const float* __restrict__ g, int ld, int k0, int col0,
                                      int t, float4 st[2]) {
    int kq = t & 3, cg = (t >> 2) & 15, ks = t >> 6;
    const float* p = g + (size_t)(k0 + ks * 8 + kq) * ld + col0 + cg * 4;
    st[0] = ld4(p);
    st[1] = ld4(p + (size_t)4 * ld);
}
__device__ __forceinline__ void stsBD(float2* bSm, int t, const float4 st[2]) {
    int kq = t & 3, cg = (t >> 2) & 15, ks = t >> 6;
    int base = (ks * 64 + cg * 4) * 4 + (kq ^ (cg & 3));
    bSm[base + 0]  = make_float2(st[0].x, st[1].x);
    bSm[base + 4]  = make_float2(st[0].y, st[1].y);
    bSm[base + 8]  = make_float2(st[0].z, st[1].z);
    bSm[base + 12] = make_float2(st[0].w, st[1].w);
}
__device__ __forceinline__ void ldgBT(const float* __restrict__ g, int ld, int row0, int k0,
                                      int t, float4 st[2]) {
    int cc = t & 63, ks = t >> 6;
    const float* p = g + (size_t)(row0 + cc) * ld + k0 + ks * 8;
    st[0] = ld4(p);
    st[1] = ld4(p + 4);
}
__device__ __forceinline__ void stsBT(float2* bSm, int t, const float4 st[2]) {
    int cc = t & 63, ks = t >> 6;
    int sw = (cc >> 2) & 3;
    int base = (ks * 64 + cc) * 4;
    bSm[base + (0 ^ sw)] = make_float2(st[0].x, st[1].x);
    bSm[base + (1 ^ sw)] = make_float2(st[0].y, st[1].y);
    bSm[base + (2 ^ sw)] = make_float2(st[0].z, st[1].z);
    bSm[base + (3 ^ sw)] = make_float2(st[0].w, st[1].w);
}

// --------------------------- B smem, 128 cols (gmat) -------------------------
__device__ __forceinline__ void ldgBD128(const float* __restrict__ g, int ld, int k0, int col0,
                                         int t, float4 st[4]) {
#pragma unroll
    for (int uu = 0; uu < 2; ++uu) {
        int u = t + uu * 128;
        int kq = u & 3, cg = (u >> 2) & 31, ks = u >> 7;
        const float* p = g + (size_t)(k0 + ks * 8 + kq) * ld + col0 + cg * 4;
        st[uu * 2 + 0] = ld4(p);
        st[uu * 2 + 1] = ld4(p + (size_t)4 * ld);
    }
}
__device__ __forceinline__ void stsBD128(float2* bSm, int t, const float4 st[4]) {
#pragma unroll
    for (int uu = 0; uu < 2; ++uu) {
        int u = t + uu * 128;
        int kq = u & 3, cg = (u >> 2) & 31, ks = u >> 7;
        int base = ((ks << 7) + cg * 4) * 4 + (kq ^ (cg & 3));
        float4 lo = st[uu * 2 + 0], hi = st[uu * 2 + 1];
        bSm[base + 0]  = make_float2(lo.x, hi.x);
        bSm[base + 4]  = make_float2(lo.y, hi.y);
        bSm[base + 8]  = make_float2(lo.z, hi.z);
        bSm[base + 12] = make_float2(lo.w, hi.w);
    }
}

// ---------------------------------------------------------------------------
// Compute chunks. 2xTF32 split: acc += Ah*Bh + Al*Bh.
// ---------------------------------------------------------------------------
__device__ __forceinline__ void computeChunk(const float4* __restrict__ aSm,
                                             const float2* __restrict__ bSm,
                                             int mBase, int nBase, int lane,
                                             float acc[4][4][4]) {
    const int sl  = lane ^ ((lane >> 3) & 3);
    const int kqc = lane & 3;
    const int cr  = lane >> 2;
    const int mg0 = mBase >> 4;
#pragma unroll
    for (int ks = 0; ks < 2; ++ks) {
        uint32_t ah[4][4], al[4][4];
#pragma unroll
        for (int mt = 0; mt < 4; ++mt) {
            float4 fa = aSm[(ks * 8 + mg0 + mt) * 32 + sl];
            splitu(fa.x, ah[mt][0], al[mt][0]);
            splitu(fa.y, ah[mt][1], al[mt][1]);
            splitu(fa.z, ah[mt][2], al[mt][2]);
            splitu(fa.w, ah[mt][3], al[mt][3]);
        }
#pragma unroll
        for (int nt = 0; nt < 4; ++nt) {
            int cc = nBase + nt * 8 + cr;
            float2 fb = bSm[(ks * 64 + cc) * 4 + (kqc ^ ((cc >> 2) & 3))];
            uint32_t bh0 = to_tf32(fb.x);
            uint32_t bh1 = to_tf32(fb.y);
#pragma unroll
            for (int mt = 0; mt < 4; ++mt) {
                mma_tf32(acc[mt][nt], ah[mt][0], ah[mt][1], ah[mt][2], ah[mt][3], bh0, bh1);
                mma_tf32(acc[mt][nt], al[mt][0], al[mt][1], al[mt][2], al[mt][3], bh0, bh1);
            }
        }
    }
}

__device__ __forceinline__ void computeChunk128(const float4* __restrict__ aSm,
                                                const float2* __restrict__ bSm,
                                                int mBase, int nBase, int lane,
                                                float acc[4][8][4]) {
    const int sl  = lane ^ ((lane >> 3) & 3);
    const int kqc = lane & 3;
    const int cr  = lane >> 2;
    const int mg0 = mBase >> 4;
#pragma unroll
    for (int ks = 0; ks < 2; ++ks) {
        uint32_t ah[4][4], al[4][4];
#pragma unroll
        for (int mt = 0; mt < 4; ++mt) {
            float4 fa = aSm[(ks * 8 + mg0 + mt) * 32 + sl];
            splitu(fa.x, ah[mt][0], al[mt][0]);
            splitu(fa.y, ah[mt][1], al[mt][1]);
            splitu(fa.z, ah[mt][2], al[mt][2]);
            splitu(fa.w, ah[mt][3], al[mt][3]);
        }
#pragma unroll
        for (int nt = 0; nt < 8; ++nt) {
            int cc = nBase + nt * 8 + cr;
            float2 fb = bSm[((ks << 7) + cc) * 4 + (kqc ^ ((cc >> 2) & 3))];
            uint32_t bh0 = to_tf32(fb.x);
            uint32_t bh1 = to_tf32(fb.y);
#pragma unroll
            for (int mt = 0; mt < 4; ++mt) {
                mma_tf32(acc[mt][nt], ah[mt][0], ah[mt][1], ah[mt][2], ah[mt][3], bh0, bh1);
                mma_tf32(acc[mt][nt], al[mt][0], al[mt][1], al[mt][2], al[mt][3], bh0, bh1);
            }
        }
    }
}

#define INIT_ACC4(acc) \
    _Pragma("unroll") for (int _a = 0; _a < 4; ++_a) \
    _Pragma("unroll") for (int _b = 0; _b < 4; ++_b) \
    _Pragma("unroll") for (int _d = 0; _d < 4; ++_d) acc[_a][_b][_d] = 0.f

#define INIT_ACC8(acc) \
    _Pragma("unroll") for (int _a = 0; _a < 4; ++_a) \
    _Pragma("unroll") for (int _b = 0; _b < 8; ++_b) \
    _Pragma("unroll") for (int _d = 0; _d < 4; ++_d) acc[_a][_b][_d] = 0.f

// ---------------------------------------------------------------------------
// Kernel 1: projections + decay folding. grid (128, 4, 3), block 128.
// ---------------------------------------------------------------------------
__global__ __launch_bounds__(128, 3)
void proj_kernel(const float* __restrict__ xq, const float* __restrict__ xk,
                 const float* __restrict__ xv,
                 const float* __restrict__ Wq, const float* __restrict__ Wk,
                 const float* __restrict__ Wv,
                 float sScale, float log2gi) {
    __shared__ float4 aSm[1024];
    __shared__ float2 bSm[1024];
    const int tid = threadIdx.x, lane = tid & 31, warp = tid >> 5;
    const int mBase = (warp >> 1) * 64, nBase = (warp & 1) * 32;
    const int row0 = blockIdx.x * 128, col0 = blockIdx.y * 64;
    const int z = blockIdx.z;

    const float* X; const float* W; float* O;
    if (z == 0)      { X = xq; W = Wq; O = g_Q; }
    else if (z == 1) { X = xk; W = Wk; O = g_K; }
    else             { X = xv; W = Wv; O = g_V; }

    float acc[4][4][4];
    INIT_ACC4(acc);
    {
        float4 stA[4], stB[2];
        ldgA(X, DIN, row0, 0, tid, stA);
        ldgBD(W, DIMN, 0, col0, tid, stB);
        stsA(aSm, tid, stA);
        stsBD(bSm, tid, stB);
        for (int c = 0; c < DIN / 16; ++c) {
            __syncthreads();
            const bool more = (c + 1) < DIN / 16;
            if (more) {
                ldgA(X, DIN, row0, (c + 1) * 16, tid, stA);
                ldgBD(W, DIMN, (c + 1) * 16, col0, tid, stB);
            }
            computeChunk(aSm + (c & 1) * 512, bSm + (c & 1) * 512, mBase, nBase, lane, acc);
            if (more) {
                stsA(aSm + ((c + 1) & 1) * 512, tid, stA);
                stsBD(bSm + ((c + 1) & 1) * 512, tid, stB);
            }
        }
    }

#pragma unroll
    for (int mt = 0; mt < 4; ++mt) {
        const int r = row0 + mBase + mt * 16 + (lane >> 2);
        float f0 = 1.f, f1 = 1.f;
        if (z == 0) {
            f0 = sScale * exp2f((float)(r & (SS - 1)) * log2gi);
            f1 = sScale * exp2f((float)((r + 8) & (SS - 1)) * log2gi);
        } else if (z == 1) {
            f0 = sScale * exp2f(-(float)(r & (SS - 1)) * log2gi);
            f1 = sScale * exp2f(-(float)((r + 8) & (SS - 1)) * log2gi);
        }
#pragma unroll
        for (int nt = 0; nt < 4; ++nt) {
            int cc = col0 + nBase + nt * 8 + (lane & 3) * 2;
            *reinterpret_cast<float2*>(O + (size_t)r * DIMN + cc) =
                make_float2(acc[mt][nt][0] * f0, acc[mt][nt][1] * f0);
            *reinterpret_cast<float2*>(O + (size_t)(r + 8) * DIMN + cc) =
                make_float2(acc[mt][nt][2] * f1, acc[mt][nt][3] * f1);
        }
    }
}

// ---------------------------------------------------------------------------
// segsum + kpre: K column sums / exclusive chunk prefix.
// ---------------------------------------------------------------------------
__global__ void segsum_kernel() {          // grid (64, 8), block 256
    const int seg = blockIdx.x, b = blockIdx.y, d = threadIdx.x;
    const float* p = g_K + ((size_t)b * SS + seg * 32) * DIMN + d;
    float s = 0.f;
#pragma unroll 8
    for (int k = 0; k < 32; ++k) s += p[(size_t)k * DIMN];
    g_segsum[((size_t)b * 64 + seg) * DIMN + d] = s;
}
__global__ void kpre_kernel() {            // grid 8, block 256
    const int b = blockIdx.x, d = threadIdx.x;
    float run = 0.f;
    for (int c = 0; c < NCH; ++c) {
        g_ksum[((size_t)b * NCH + c) * DIMN + d] = run;
        const float* sp = g_segsum + ((size_t)b * 64 + c * 4) * DIMN + d;
        run += sp[0] + sp[(size_t)DIMN] + sp[(size_t)2 * DIMN] + sp[(size_t)3 * DIMN];
    }
}

// ---------------------------------------------------------------------------
// diag: tril(Qt_c Kt_c^T) in column halves. grid (16, 2, 8), block 128.
// Warp tile 64x32; emits per-half row sums -> g_dsumP[half].
// ---------------------------------------------------------------------------
__global__ __launch_bounds__(128, 3)
void diag_kernel() {
    __shared__ float4 aSm[1024];
    __shared__ float2 bSm[1024];
    __shared__ float rowAcc[128];
    const int tid = threadIdx.x, lane = tid & 31, warp = tid >> 5;
    const int mBase = (warp >> 1) * 64, nBase = (warp & 1) * 32;
    const int c = blockIdx.x, nh = blockIdx.y, b = blockIdx.z;

    const float* Qp = g_Q + (size_t)b * SS * DIMN;
    const float* Kp = g_K + (size_t)b * SS * DIMN;
    const int krow0 = c * 128 + nh * 64;

    rowAcc[tid] = 0.f;

    float acc[4][4][4];
    INIT_ACC4(acc);
    {
        float4 stA[4], stB[2];
        ldgA(Qp, DIMN, c * 128, 0, tid, stA);
        ldgBT(Kp, DIMN, krow0, 0, tid, stB);
        stsA(aSm, tid, stA);
        stsBT(bSm, tid, stB);
        for (int ci = 0; ci < 16; ++ci) {
            __syncthreads();
            const bool more = (ci + 1) < 16;
            if (more) {
                ldgA(Qp, DIMN, c * 128, (ci + 1) * 16, tid, stA);
                ldgBT(Kp, DIMN, krow0, (ci + 1) * 16, tid, stB);
            }
            computeChunk(aSm + (ci & 1) * 512, bSm + (ci & 1) * 512, mBase, nBase, lane, acc);
            if (more) {
                stsA(aSm + ((ci + 1) & 1) * 512, tid, stA);
                stsBT(bSm + ((ci + 1) & 1) * 512, tid, stB);
            }
        }
    }

    float* Dp = g_diag + ((size_t)(b * NCH + c)) * 128 * 128;
#pragma unroll
    for (int mt = 0; mt < 4; ++mt)
#pragma unroll
        for (int h = 0; h < 2; ++h) {
            const int lr = mBase + mt * 16 + h * 8 + (lane >> 2);
            float rsum = 0.f;
#pragma unroll
            for (int nt = 0; nt < 4; ++nt) {
                const int colc = nh * 64 + nBase + nt * 8 + (lane & 3) * 2;
                const int d0 = lr - colc;
                float v0 = (d0 >= 0)     ? acc[mt][nt][h * 2 + 0] : 0.f;
                float v1 = (d0 - 1 >= 0) ? acc[mt][nt][h * 2 + 1] : 0.f;
                *reinterpret_cast<float2*>(Dp + (size_t)lr * 128 + colc) = make_float2(v0, v1);
                rsum += v0 + v1;
            }
            rsum += __shfl_xor_sync(0xffffffffu, rsum, 1);
            rsum += __shfl_xor_sync(0xffffffffu, rsum, 2);
            if ((lane & 3) == 0) atomicAdd(&rowAcc[lr], rsum);  // 2 commutative adds/slot
        }
    __syncthreads();
    g_dsumP[nh][(size_t)b * SS + c * 128 + tid] = rowAcc[tid];
}

// ---------------------------------------------------------------------------
// denomv: denom[i] = dsumP0+dsumP1 + Qt_i.ksumExcl; scales V in place.
// grid 2048, block 256 (warp per row).
// ---------------------------------------------------------------------------
__global__ void denomv_kernel() {
    const int row = blockIdx.x * 8 + (threadIdx.x >> 5);
    const int lane = threadIdx.x & 31;
    const int b = row >> 11, s = row & (SS - 1);
    const int c = s >> 7;
    const float* q = g_Q + (size_t)row * DIMN + lane * 8;
    const float* kp = g_ksum + ((size_t)b * NCH + c) * DIMN + lane * 8;
    float sum = 0.f;
#pragma unroll
    for (int i = 0; i < 8; i += 4) {
        float4 a = ld4(q + i), v = ld4(kp + i);
        sum += a.x * v.x + a.y * v.y + a.z * v.z + a.w * v.w;
    }
#pragma unroll
    for (int o = 16; o; o >>= 1) sum += __shfl_xor_sync(0xffffffffu, sum, o);
    sum += g_dsumP[0][row] + g_dsumP[1][row];
    const float inv = 1.f / fmaxf(fabsf(sum), 1.f);
    float* vrow = g_V + (size_t)row * DIMN + lane * 8;
#pragma unroll
    for (int i = 0; i < 8; i += 4) {
        float4 v = ld4(vrow + i);
        *reinterpret_cast<float4*>(vrow + i) =
            make_float4(v.x * inv, v.y * inv, v.z * inv, v.w * inv);
    }
}

// ---------------------------------------------------------------------------
// Transpose Kt -> g_KT[b][dk][s]. grid (64, 8, 8), block (32, 8).
// ---------------------------------------------------------------------------
__global__ void ktrans_kernel() {
    __shared__ float tile[32][33];
    const int b = blockIdx.z;
    const int s0 = blockIdx.x * 32, d0 = blockIdx.y * 32;
    const float* Kp = g_K + (size_t)b * SS * DIMN;
    float* Tp = g_KT + (size_t)b * DIMN * SS;
#pragma unroll
    for (int r = 0; r < 32; r += 8)
        tile[threadIdx.y + r][threadIdx.x] =
            Kp[(size_t)(s0 + threadIdx.y + r) * DIMN + d0 + threadIdx.x];
    __syncthreads();
#pragma unroll
    for (int r = 0; r < 32; r += 8)
        Tp[(size_t)(d0 + threadIdx.y + r) * SS + s0 + threadIdx.x] =
            tile[threadIdx.x][threadIdx.y + r];
}

// ---------------------------------------------------------------------------
// gmat: G_c = Kt_c^T V'_c  [256x256]. grid (4, 16, 8), block 128.
// ---------------------------------------------------------------------------
__global__ __launch_bounds__(128)
void gmat_kernel() {
    __shared__ float4 aSm[1024];
    __shared__ float2 bSm[2048];
    const int tid = threadIdx.x, lane = tid & 31, warp = tid >> 5;
    const int mBase = (warp >> 1) * 64, nBase = (warp & 1) * 64;
    const int mtile = blockIdx.x & 1, ntile = blockIdx.x >> 1;
    const int c = blockIdx.y, b = blockIdx.z;

    const float* Ap = g_KT + (size_t)b * DIMN * SS;
    const float* Vp = g_V + (size_t)b * SS * DIMN;

    float acc[4][8][4];
    INIT_ACC8(acc);
    {
        float4 stA[4], stB[4];
        ldgA(Ap, SS, mtile * 128, c * 128, tid, stA);
        ldgBD128(Vp, DIMN, c * 128, ntile * 128, tid, stB);
        stsA(aSm, tid, stA);
        stsBD128(bSm, tid, stB);
        for (int ci = 0; ci < 8; ++ci) {
            __syncthreads();
            const bool more = (ci + 1) < 8;
            if (more) {
                const int k0 = c * 128 + (ci + 1) * 16;
                ldgA(Ap, SS, mtile * 128, k0, tid, stA);
                ldgBD128(Vp, DIMN, k0, ntile * 128, tid, stB);
            }
            computeChunk128(aSm + (ci & 1) * 512, bSm + (ci & 1) * 1024, mBase, nBase, lane, acc);
            if (more) {
                stsA(aSm + ((ci + 1) & 1) * 512, tid, stA);
                stsBD128(bSm + ((ci + 1) & 1) * 1024, tid, stB);
            }
        }
    }

    float* Gp = g_G + ((size_t)(b * NCH + c)) * DIMN * DIMN;
#pragma unroll
    for (int mt = 0; mt < 4; ++mt)
#pragma unroll
        for (int nt = 0; nt < 8; ++nt) {
            int r  = mtile * 128 + mBase + mt * 16 + (lane >> 2);
            int cc = ntile * 128 + nBase + nt * 8 + (lane & 3) * 2;
            *reinterpret_cast<float2*>(Gp + (size_t)r * DIMN + cc) =
                make_float2(acc[mt][nt][0], acc[mt][nt][1]);
            *reinterpret_cast<float2*>(Gp + (size_t)(r + 8) * DIMN + cc) =
                make_float2(acc[mt][nt][2], acc[mt][nt][3]);
        }
}

// ---------------------------------------------------------------------------
// sprefix: S_c = sum_{c'<c} G_c' (exclusive). grid (128, 8), block 128.
// ---------------------------------------------------------------------------
__global__ void sprefix_kernel() {
    const int b = blockIdx.y;
    const size_t e = ((size_t)blockIdx.x * 128 + threadIdx.x) * 4;
    float4 run = make_float4(0.f, 0.f, 0.f, 0.f);
    for (int c = 0; c < NCH; ++c) {
        const size_t idx = ((size_t)(b * NCH + c)) * DIMN * DIMN + e;
        *reinterpret_cast<float4*>(&g_S[idx]) = run;
        float4 gval = ld4(&g_G[idx]);
        run.x += gval.x; run.y += gval.y; run.z += gval.z; run.w += gval.w;
    }
}

// ---------------------------------------------------------------------------
// Fused out in column quarters: out_c = Qt_c @ S_c + diag_c @ V'_c.
// grid (16, 4, 8), block 128, warp tile 64x32. 24 unified k16 chunks.
// ---------------------------------------------------------------------------
__global__ __launch_bounds__(128, 3)
void outfused_kernel(float* __restrict__ out) {
    __shared__ float4 aSm[1024];
    __shared__ float2 bSm[1024];
    const int tid = threadIdx.x, lane = tid & 31, warp = tid >> 5;
    const int mBase = (warp >> 1) * 64, nBase = (warp & 1) * 32;
    const int c = blockIdx.x, q4 = blockIdx.y, b = blockIdx.z;
    const int col0 = q4 * 64;

    const float* Qp = g_Q + (size_t)b * SS * DIMN;
    const float* Sp = g_S + ((size_t)(b * NCH + c)) * DIMN * DIMN;
    const float* Dp = g_diag + ((size_t)(b * NCH + c)) * 128 * 128;
    const float* Vp = g_V + (size_t)b * SS * DIMN;

    auto loadChunk = [&](int ci, float4 stA[4], float4 stB[2]) {
        if (ci < 16) {
            ldgA(Qp, DIMN, c * 128, ci * 16, tid, stA);
            ldgBD(Sp, DIMN, ci * 16, col0, tid, stB);
        } else {
            const int kk = (ci - 16) * 16;
            ldgA(Dp, 128, 0, kk, tid, stA);
            ldgBD(Vp, DIMN, c * 128 + kk, col0, tid, stB);
        }
    };

    float acc[4][4][4];
    INIT_ACC4(acc);
    {
        float4 stA[4], stB[2];
        loadChunk(0, stA, stB);
        stsA(aSm, tid, stA);
        stsBD(bSm, tid, stB);
        for (int ci = 0; ci < 24; ++ci) {
            __syncthreads();
            const bool more = (ci + 1) < 24;
            if (more) loadChunk(ci + 1, stA, stB);
            computeChunk(aSm + (ci & 1) * 512, bSm + (ci & 1) * 512, mBase, nBase, lane, acc);
            if (more) {
                stsA(aSm + ((ci + 1) & 1) * 512, tid, stA);
                stsBD(bSm + ((ci + 1) & 1) * 512, tid, stB);
            }
        }
    }

    float* Ob = out + (size_t)b * SS * DIMN;
#pragma unroll
    for (int mt = 0; mt < 4; ++mt)
#pragma unroll
        for (int nt = 0; nt < 4; ++nt) {
            int r  = c * 128 + mBase + mt * 16 + (lane >> 2);
            int cc = col0 + nBase + nt * 8 + (lane & 3) * 2;
            *reinterpret_cast<float2*>(Ob + (size_t)r * DIMN + cc) =
                make_float2(acc[mt][nt][0], acc[mt][nt][1]);
            *reinterpret_cast<float2*>(Ob + (size_t)(r + 8) * DIMN + cc) =
                make_float2(acc[mt][nt][2], acc[mt][nt][3]);
        }
}

// ---------------------------------------------------------------------------
// Launch
// ---------------------------------------------------------------------------
extern "C" void kernel_launch(void* const* d_in, const int* in_sizes, int n_in,
                              void* d_out, int out_size) {
    const float* xq = (const float*)d_in[0];
    const float* xk = (const float*)d_in[1];
    const float* xv = (const float*)d_in[2];
    const float* Wq = (const float*)d_in[3];
    const float* Wk = (const float*)d_in[4];
    const float* Wv = (const float*)d_in[5];
    float* out = (float*)d_out;

    double acc = 0.0, gp = 1.0;
    const double ginv = 1.0 / GAMMA;
    for (int d = 0; d < SS; ++d) { acc += (double)(SS - d) * gp; gp *= ginv; }
    const double scoreScale = 1.0 / (sqrt(acc) * 16.0);
    const float sScale = (float)sqrt(scoreScale);
    const float log2gi = (float)(-log(GAMMA) / log(2.0));

    proj_kernel<<<dim3(128, 4, 3), 128>>>(xq, xk, xv, Wq, Wk, Wv, sScale, log2gi);
    segsum_kernel<<<dim3(64, 8), 256>>>();
    kpre_kernel<<<8, 256>>>();
    diag_kernel<<<dim3(16, 2, 8), 128>>>();
    denomv_kernel<<<2048, 256>>>();
    ktrans_kernel<<<dim3(64, 8, 8), dim3(32, 8)>>>();
    gmat_kernel<<<dim3(4, 16, 8), 128>>>();
    sprefix_kernel<<<dim3(128, 8), 128>>>();
    outfused_kernel<<<dim3(16, 4, 8), 128>>>(out);
}